// round 13
// baseline (speedup 1.0000x reference)
#include <cuda_runtime.h>
#include <cuda_fp16.h>
#include <cstdint>

#define N_DIM 512

// ---------------- scratch ----------------
__device__ __half g_P[(size_t)100000 * 128];   // fp16 P (25.6MB): [0..63]=s, [64..127]=o

// ---------------- smem geometry (2-stage, pass = 4 x M64 units, K-chunk=64) ----------------
// A: 256 rows x 256B fp32 (64 floats), XOR-parity swizzled, no pad
// B: 128 rows x 256B fp32 (64 floats), same swizzle
#define A_STAGE_B 65536
#define B_STAGE_B 32768
#define B_OFF     (2 * A_STAGE_B)              // 131072
#define SMEM_BYTES (2 * A_STAGE_B + 2 * B_STAGE_B)   // 196608

// ---------------- helpers ----------------
__device__ __forceinline__ void cp16(uint32_t saddr, const void* g) {
    asm volatile("cp.async.cg.shared.global [%0], [%1], 16;" :: "r"(saddr), "l"(g));
}
__device__ __forceinline__ void cp_commit() {
    asm volatile("cp.async.commit_group;" ::: "memory");
}
template <int N>
__device__ __forceinline__ void cp_wait() {
    asm volatile("cp.async.wait_group %0;" :: "n"(N) : "memory");
}
__device__ __forceinline__ uint32_t smem_u32(const void* p) {
    uint32_t a;
    asm("{ .reg .u64 t; cvta.to.shared.u64 t, %1; cvt.u32.u64 %0, t; }" : "=r"(a) : "l"(p));
    return a;
}
__device__ __forceinline__ void hmma16816(float d[4], const uint32_t a[4], uint32_t b0, uint32_t b1) {
    asm volatile("mma.sync.aligned.m16n8k16.row.col.f32.f16.f16.f32 "
                 "{%0,%1,%2,%3},{%4,%5,%6,%7},{%8,%9},{%0,%1,%2,%3};"
                 : "+f"(d[0]), "+f"(d[1]), "+f"(d[2]), "+f"(d[3])
                 : "r"(a[0]), "r"(a[1]), "r"(a[2]), "r"(a[3]), "r"(b0), "r"(b1));
}
__device__ __forceinline__ uint32_t pack_h2(float x, float y) {
    __half2 h = __floats2half2_rn(x, y);
    return *reinterpret_cast<uint32_t*>(&h);
}

// ---------------- kernel 1: P = emb @ B^T; 4 x M64 units per pass; B from W fp32 ----------------
__global__ __launch_bounds__(512, 1) void gemm_kernel(const float* __restrict__ emb,
                                                      const float* __restrict__ W,
                                                      int n_nodes, int nunits, int grid) {
    extern __shared__ char smem[];
    const uint32_t sb = smem_u32(smem);
    const int tid = threadIdx.x;
    const int lane = tid & 31;
    const int wid = tid >> 5;
    const int wm = wid & 7;     // 8 M-tiles of 32 (pass M=256 = 4 units x 64 rows)
    const int wn = wid >> 3;    // 2 N-tiles of 64
    const int bid = blockIdx.x;

    const int cnt = (nunits - bid + grid - 1) / grid;   // units for this CTA (10 or 11)
    const int npass = (cnt + 3) >> 2;
    const int gtot = npass * 8;

    // producer: global chunk g -> (pass, kchunk c), into slot g%2
    auto ISSUE = [&](int g) {
        if (g >= gtot) return;
        const int pass = g >> 3;
        const int c = g & 7;
        const uint32_t aBase = sb + (g & 1) * A_STAGE_B;
        const uint32_t bBase = sb + B_OFF + (g & 1) * B_STAGE_B;
        #pragma unroll
        for (int i = 0; i < 8; i++) {           // A: 4096 granules of 16B
            int gr = tid + i * 512;
            int row = gr >> 4, col = gr & 15;   // row 0..255, col 0..15
            int j = pass * 4 + (row >> 6);      // quarter index within my unit list
            int unit = bid + j * grid;
            int ar = (unit < nunits) ? unit * 64 + (row & 63) : 0;
            if (ar >= n_nodes) ar = n_nodes - 1;
            cp16(aBase + row * 256 + (((uint32_t)col * 16) ^ ((row & 1) << 6)) - ((row & 1) ? 64 : 0) + ((row & 1) ? 64 : 0),  // placeholder removed below
                 emb + (size_t)ar * N_DIM + c * 64 + col * 4);
        }
        #pragma unroll
        for (int i = 0; i < 4; i++) {           // B: 2048 granules from W (L2-resident)
            int gr = tid + i * 512;
            int row = gr >> 4, col = gr & 15;   // row 0..127 = B row n
            const float* src = (row < 64) ? (W + (size_t)row * 1024)
                                          : (W + (size_t)(row - 64) * 1024 + 512);
            cp16(bBase + row * 256 + (((uint32_t)col * 16) ^ (((uint32_t)row & 1) << 6)),
                 src + c * 64 + col * 4);
        }
    };
    // NOTE on A swizzle: granule col XOR'd with ((row&1)<<2) in granule units = <<6 in bytes.
    // (The A loop above uses the same formula as B; the '- +' no-op keeps the expression identical.)

    float acc[2][8][4];
    #pragma unroll
    for (int i = 0; i < 2; i++)
        #pragma unroll
        for (int j = 0; j < 8; j++)
            #pragma unroll
            for (int k = 0; k < 4; k++) acc[i][j][k] = 0.0f;

    ISSUE(0); cp_commit();

    const int q = lane & 3;
    const int octr = lane >> 2;
    const uint32_t axm = ((uint32_t)octr & 1) << 6;   // consumed rows have row&1 == octr&1

    for (int g = 0; g < gtot; g++) {
        cp_wait<0>();
        __syncthreads();          // stage-g visible; all warps done with g-1 -> slot (g+1)%2 free
        ISSUE(g + 1);
        cp_commit();              // overlaps consume below

        const uint32_t aOff = (g & 1) * A_STAGE_B;
        const uint32_t bOff = B_OFF + (g & 1) * B_STAGE_B;

        #pragma unroll
        for (int ks = 0; ks < 4; ks++) {
            const uint32_t cx = ((uint32_t)(ks * 64 + q * 16)) ^ axm;
            // A frags: sigma k-permuted LDS.128 + cvt
            uint32_t afr[2][4];
            #pragma unroll
            for (int mt = 0; mt < 2; mt++) {
                const int r0 = wm * 32 + mt * 16 + octr;
                const float4 v0 = *(const float4*)(smem + aOff + r0 * 256 + cx);
                const float4 v1 = *(const float4*)(smem + aOff + (r0 + 8) * 256 + cx);
                afr[mt][0] = pack_h2(v0.x, v0.y);
                afr[mt][1] = pack_h2(v1.x, v1.y);
                afr[mt][2] = pack_h2(v0.z, v0.w);
                afr[mt][3] = pack_h2(v1.z, v1.w);
            }
            // B frags: fp32 LDS.128 + cvt, same sigma
            uint32_t bfr[8][2];
            #pragma unroll
            for (int nf = 0; nf < 8; nf++) {
                const int n = wn * 64 + nf * 8 + octr;
                const float4 v = *(const float4*)(smem + bOff + n * 256 + cx);
                bfr[nf][0] = pack_h2(v.x, v.y);
                bfr[nf][1] = pack_h2(v.z, v.w);
            }
            #pragma unroll
            for (int mt = 0; mt < 2; mt++)
                #pragma unroll
                for (int nf = 0; nf < 8; nf++)
                    hmma16816(acc[mt][nf], afr[mt], bfr[nf][0], bfr[nf][1]);
        }

        if ((g & 7) == 7) {
            // epilogue: each warp's quarter = wm>>1
            const int pass = g >> 3;
            const int unit = bid + (pass * 4 + (wm >> 1)) * grid;
            if (unit < nunits) {
                const int base = unit * 64 + (wm & 1) * 32;
                #pragma unroll
                for (int mt = 0; mt < 2; mt++) {
                    const int r0 = base + mt * 16 + (lane >> 2);
                    const int r1 = r0 + 8;
                    #pragma unroll
                    for (int nf = 0; nf < 8; nf++) {
                        const int col = wn * 64 + nf * 8 + (lane & 3) * 2;
                        if (r0 < n_nodes)
                            *(uint32_t*)&g_P[(size_t)r0 * 128 + col] = pack_h2(acc[0][nf][0], acc[0][nf][1]);
                        if (r1 < n_nodes)
                            *(uint32_t*)&g_P[(size_t)r1 * 128 + col] = pack_h2(acc[0][nf][2], acc[0][nf][3]);
                        // mt handled via acc[mt]: unrolled below
                    }
                }
            }
            // clear accumulators (and fix mt indexing: do stores for mt=1 too)
            if (unit < nunits) {
                const int base = unit * 64 + (wm & 1) * 32;
                #pragma unroll
                for (int nf = 0; nf < 8; nf++) {
                    const int col = wn * 64 + nf * 8 + (lane & 3) * 2;
                    const int r0 = base + 16 + (lane >> 2);
                    const int r1 = r0 + 8;
                    if (r0 < n_nodes)
                        *(uint32_t*)&g_P[(size_t)r0 * 128 + col] = pack_h2(acc[1][nf][0], acc[1][nf][1]);
                    if (r1 < n_nodes)
                        *(uint32_t*)&g_P[(size_t)r1 * 128 + col] = pack_h2(acc[1][nf][2], acc[1][nf][3]);
                }
            }
            #pragma unroll
            for (int mt = 0; mt < 2; mt++)
                #pragma unroll
                for (int nf = 0; nf < 8; nf++)
                    #pragma unroll
                    for (int k = 0; k < 4; k++) acc[mt][nf][k] = 0.0f;
        }
    }
}

// ---------------- kernel 2: per-triple gather-combine, 2 triples/thread, fp16 P ----------------
__global__ __launch_bounds__(256) void gather_kernel(const int* __restrict__ triples,
                                                     const float* __restrict__ b,
                                                     float* __restrict__ out, int n) {
    int t = blockIdx.x * blockDim.x + threadIdx.x;
    int half = (n + 1) >> 1;
    if (t >= half) return;
    int t2 = t + half;
    bool has2 = t2 < n;

    int s1 = triples[t],  r1 = triples[n + t],  o1 = triples[2 * n + t];
    int s2 = 0, r2 = 0, o2 = 0;
    if (has2) { s2 = triples[t2]; r2 = triples[n + t2]; o2 = triples[2 * n + t2]; }

    __half a1 = __ldg(&g_P[(size_t)s1 * 128 + r1]);
    __half c1 = __ldg(&g_P[(size_t)o1 * 128 + 64 + r1]);
    __half a2 = __float2half(0.f), c2 = __float2half(0.f);
    if (has2) {
        a2 = __ldg(&g_P[(size_t)s2 * 128 + r2]);
        c2 = __ldg(&g_P[(size_t)o2 * 128 + 64 + r2]);
    }

    out[t] = __half2float(a1) + __half2float(c1) + __ldg(&b[r1]);
    if (has2) out[t2] = __half2float(a2) + __half2float(c2) + __ldg(&b[r2]);
}

extern "C" void kernel_launch(void* const* d_in, const int* in_sizes, int n_in,
                              void* d_out, int out_size)
{
    const float* emb     = (const float*)d_in[0];
    const float* W       = (const float*)d_in[1];
    const float* b       = (const float*)d_in[2];
    const int*   triples = (const int*)d_in[3];
    float*       out     = (float*)d_out;

    int n_nodes = in_sizes[0] / N_DIM;        // 100000
    int n_tr    = in_sizes[3] / 3;            // 200000
    int nunits  = (n_nodes + 63) / 64;        // 1563 M64 units

    static int nsm = 0;
    if (nsm == 0) {
        cudaDeviceGetAttribute(&nsm, cudaDevAttrMultiProcessorCount, 0);
        cudaFuncSetAttribute(gemm_kernel, cudaFuncAttributeMaxDynamicSharedMemorySize, SMEM_BYTES);
    }
    int grid = nsm;
    if (grid * 4 > nunits) grid = (nunits + 3) / 4;

    gemm_kernel<<<grid, 512, SMEM_BYTES>>>(emb, W, n_nodes, nunits, grid);
    gather_kernel<<<((n_tr + 1) / 2 + 255) / 256, 256>>>(triples, b, out, n_tr);
}

// round 14
// speedup vs baseline: 1.1298x; 1.1298x over previous
#include <cuda_runtime.h>
#include <cuda_fp16.h>
#include <cstdint>

#define N_DIM 512

// ---------------- scratch ----------------
__device__ __half g_Bh[128 * 512];             // fp16 W: rows 0..63 = Ws, 64..127 = Wo
__device__ __half g_P[(size_t)100000 * 128];   // fp16 P (25.6MB): [0..63]=s, [64..127]=o

// ---------------- smem geometry (2-stage, M=192 tile, K-chunk=64, all fp16 128B rows) ----------------
#define A_STAGE_B 24576                        // 192 rows x 128B fp16
#define B_STAGE_B 16384                        // 128 rows x 128B fp16
#define B_OFF     (2 * A_STAGE_B)              // 49152
#define SMEM_BYTES (2 * A_STAGE_B + 2 * B_STAGE_B)   // 81920

// smem swizzle: 16B-granule byte col c in row r -> c ^ ((r&7)*16)
#define FSW(r) ((uint32_t)(((r) & 7) << 4))

// ---------------- helpers ----------------
__device__ __forceinline__ void cp16(uint32_t saddr, const void* g) {
    asm volatile("cp.async.cg.shared.global [%0], [%1], 16;" :: "r"(saddr), "l"(g));
}
__device__ __forceinline__ void cp_commit() {
    asm volatile("cp.async.commit_group;" ::: "memory");
}
template <int N>
__device__ __forceinline__ void cp_wait() {
    asm volatile("cp.async.wait_group %0;" :: "n"(N) : "memory");
}
__device__ __forceinline__ uint32_t smem_u32(const void* p) {
    uint32_t a;
    asm("{ .reg .u64 t; cvta.to.shared.u64 t, %1; cvt.u32.u64 %0, t; }" : "=r"(a) : "l"(p));
    return a;
}
__device__ __forceinline__ void ldsm4(uint32_t r[4], uint32_t a) {
    asm volatile("ldmatrix.sync.aligned.m8n8.x4.shared.b16 {%0,%1,%2,%3}, [%4];"
                 : "=r"(r[0]), "=r"(r[1]), "=r"(r[2]), "=r"(r[3]) : "r"(a));
}
__device__ __forceinline__ void hmma16816(float d[4], const uint32_t a[4], uint32_t b0, uint32_t b1) {
    asm volatile("mma.sync.aligned.m16n8k16.row.col.f32.f16.f16.f32 "
                 "{%0,%1,%2,%3},{%4,%5,%6,%7},{%8,%9},{%0,%1,%2,%3};"
                 : "+f"(d[0]), "+f"(d[1]), "+f"(d[2]), "+f"(d[3])
                 : "r"(a[0]), "r"(a[1]), "r"(a[2]), "r"(a[3]), "r"(b0), "r"(b1));
}
__device__ __forceinline__ uint32_t pack_h2(float x, float y) {
    __half2 h = __floats2half2_rn(x, y);
    return *reinterpret_cast<uint32_t*>(&h);
}
__device__ __forceinline__ void cvt16(const float4 v[4], uint4 h[2]) {
    h[0].x = pack_h2(v[0].x, v[0].y); h[0].y = pack_h2(v[0].z, v[0].w);
    h[0].z = pack_h2(v[1].x, v[1].y); h[0].w = pack_h2(v[1].z, v[1].w);
    h[1].x = pack_h2(v[2].x, v[2].y); h[1].y = pack_h2(v[2].z, v[2].w);
    h[1].z = pack_h2(v[3].x, v[3].y); h[1].w = pack_h2(v[3].z, v[3].w);
}

// ---------------- kernel 0: W fp32 -> fp16, reorder to [128][512] ----------------
__global__ __launch_bounds__(128) void prep_kernel(const float* __restrict__ W) {
    int i = (blockIdx.x * 128 + threadIdx.x) * 2;
    if (i >= 128 * 512) return;
    int n = i >> 9, k = i & 511;
    const float* src = (n < 64) ? (W + n * 1024 + k) : (W + (n - 64) * 1024 + 512 + k);
    float2 v = *(const float2*)src;
    *(__half2*)&g_Bh[i] = __floats2half2_rn(v.x, v.y);
}

// ---------------- kernel 1: persistent P = emb @ B^T; fp16 A via LDG->cvt->STS register hop ----------------
__global__ __launch_bounds__(384, 1) void gemm_kernel(const float* __restrict__ emb,
                                                      int n_nodes, int ntiles, int grid) {
    extern __shared__ char smem[];
    const uint32_t sb = smem_u32(smem);
    const int tid = threadIdx.x;
    const int lane = tid & 31;
    const int wid = tid >> 5;
    const int wm = wid % 6;     // 6 M-tiles of 32 (CTA M=192)
    const int wn = wid / 6;     // 2 N-tiles of 64
    const int bid = blockIdx.x;

    const int ntiles_mine = (ntiles - bid + grid - 1) / grid;
    const int gtot = ntiles_mine * 8;

    // A producer mapping: thread -> (row, half-of-64-cols)
    const int arow = tid >> 1;          // 0..191
    const int ah   = tid & 1;           // 0..1 (32 floats each)
    // B producer: threads 0..255, 4 granules each
    const int brow = tid >> 1;          // 0..127 for tid<256
    const int bh   = tid & 1;

    float4 buf[8];                      // A chunk in flight (32 regs)

    auto LDGA = [&](int g) {
        if (g >= gtot) return;
        const int tile = bid + (g >> 3) * grid;
        const int c = g & 7;
        int ar = tile * 192 + arow;
        if (ar >= n_nodes) ar = n_nodes - 1;
        const float4* src = (const float4*)(emb + (size_t)ar * N_DIM + c * 64 + ah * 32);
        #pragma unroll
        for (int i = 0; i < 8; i++) buf[i] = src[i];
    };
    auto STSA = [&](int g) {
        if (g >= gtot) return;
        const uint32_t base = sb + (g & 1) * A_STAGE_B + arow * 128;
        uint4 h[2];
        cvt16(buf, h);
        *(uint4*)(smem + (base - sb) + (((uint32_t)(ah * 64 + 0))  ^ FSW(arow))) = h[0];
        *(uint4*)(smem + (base - sb) + (((uint32_t)(ah * 64 + 16)) ^ FSW(arow))) = h[1];
        cvt16(buf + 4, h);
        *(uint4*)(smem + (base - sb) + (((uint32_t)(ah * 64 + 32)) ^ FSW(arow))) = h[0];
        *(uint4*)(smem + (base - sb) + (((uint32_t)(ah * 64 + 48)) ^ FSW(arow))) = h[1];
    };
    auto ISSUEB = [&](int g) {
        if (g >= gtot || tid >= 256) return;
        const int c = g & 7;
        const uint32_t base = sb + B_OFF + (g & 1) * B_STAGE_B + brow * 128;
        const __half* src = g_Bh + brow * N_DIM + c * 64 + bh * 32;
        #pragma unroll
        for (int j = 0; j < 4; j++)
            cp16(base + (((uint32_t)(bh * 64 + j * 16)) ^ FSW(brow)), src + j * 8);
    };

    float acc[2][8][4];
    #pragma unroll
    for (int i = 0; i < 2; i++)
        #pragma unroll
        for (int j = 0; j < 8; j++)
            #pragma unroll
            for (int k = 0; k < 4; k++) acc[i][j][k] = 0.0f;

    // prologue: A0 staged, A1 in regs, B0 in flight
    LDGA(0);
    STSA(0);              // stalls on LDG data once
    LDGA(1);
    ISSUEB(0); cp_commit();

    // consumer lane constants
    const int a_lrow = lane & 15;                 // ldmatrix A row within m16
    const uint32_t a_lcol = (uint32_t)((lane >> 4) * 16);
    const int b_lrow = (lane & 7) + ((lane >> 4) & 1) * 8;   // R3-proven B lane map
    const uint32_t b_lcol = (uint32_t)(((lane >> 3) & 1) * 16);

    for (int g = 0; g < gtot; g++) {
        cp_wait<0>();        // B of chunk g complete
        __syncthreads();     // A STS of g visible; all warps done with g-1 -> slot (g+1)&1 free
        ISSUEB(g + 1); cp_commit();
        STSA(g + 1);         // from buf (LDG'd last iter)
        LDGA(g + 2);         // refill buf (program-order WAR after STSA)

        const uint32_t aOff = (g & 1) * A_STAGE_B;
        const uint32_t bOff = B_OFF + (g & 1) * B_STAGE_B;

        #pragma unroll
        for (int ks = 0; ks < 4; ks++) {
            uint32_t afr[2][4];
            #pragma unroll
            for (int mt = 0; mt < 2; mt++) {
                const int row = wm * 32 + mt * 16 + a_lrow;
                ldsm4(afr[mt], sb + aOff + row * 128 + (((uint32_t)(ks * 32) + a_lcol) ^ FSW(row)));
            }
            uint32_t bfr[4][4];
            #pragma unroll
            for (int p = 0; p < 4; p++) {
                const int rn = wn * 64 + p * 16 + b_lrow;
                ldsm4(bfr[p], sb + bOff + rn * 128 + (((uint32_t)(ks * 32) + b_lcol) ^ FSW(rn)));
            }
            #pragma unroll
            for (int mt = 0; mt < 2; mt++)
                #pragma unroll
                for (int p = 0; p < 4; p++) {
                    hmma16816(acc[mt][2 * p],     afr[mt], bfr[p][0], bfr[p][1]);
                    hmma16816(acc[mt][2 * p + 1], afr[mt], bfr[p][2], bfr[p][3]);
                }
        }

        if ((g & 7) == 7) {
            // epilogue for this tile (next tile's A/B already in flight)
            const int ctaM = (bid + (g >> 3) * grid) * 192;
            #pragma unroll
            for (int mt = 0; mt < 2; mt++) {
                const int r0 = ctaM + wm * 32 + mt * 16 + (lane >> 2);
                const int r1 = r0 + 8;
                #pragma unroll
                for (int nf = 0; nf < 8; nf++) {
                    const int col = wn * 64 + nf * 8 + (lane & 3) * 2;
                    if (r0 < n_nodes)
                        *(uint32_t*)&g_P[(size_t)r0 * 128 + col] = pack_h2(acc[mt][nf][0], acc[mt][nf][1]);
                    if (r1 < n_nodes)
                        *(uint32_t*)&g_P[(size_t)r1 * 128 + col] = pack_h2(acc[mt][nf][2], acc[mt][nf][3]);
                    acc[mt][nf][0] = acc[mt][nf][1] = acc[mt][nf][2] = acc[mt][nf][3] = 0.0f;
                }
            }
        }
    }
}

// ---------------- kernel 2: per-triple gather-combine, 2 triples/thread, fp16 P ----------------
__global__ __launch_bounds__(256) void gather_kernel(const int* __restrict__ triples,
                                                     const float* __restrict__ b,
                                                     float* __restrict__ out, int n) {
    int t = blockIdx.x * blockDim.x + threadIdx.x;
    int half = (n + 1) >> 1;
    if (t >= half) return;
    int t2 = t + half;
    bool has2 = t2 < n;

    int s1 = triples[t],  r1 = triples[n + t],  o1 = triples[2 * n + t];
    int s2 = 0, r2 = 0, o2 = 0;
    if (has2) { s2 = triples[t2]; r2 = triples[n + t2]; o2 = triples[2 * n + t2]; }

    __half a1 = __ldg(&g_P[(size_t)s1 * 128 + r1]);
    __half c1 = __ldg(&g_P[(size_t)o1 * 128 + 64 + r1]);
    __half a2 = __float2half(0.f), c2 = __float2half(0.f);
    if (has2) {
        a2 = __ldg(&g_P[(size_t)s2 * 128 + r2]);
        c2 = __ldg(&g_P[(size_t)o2 * 128 + 64 + r2]);
    }

    out[t] = __half2float(a1) + __half2float(c1) + __ldg(&b[r1]);
    if (has2) out[t2] = __half2float(a2) + __half2float(c2) + __ldg(&b[r2]);
}

extern "C" void kernel_launch(void* const* d_in, const int* in_sizes, int n_in,
                              void* d_out, int out_size)
{
    const float* emb     = (const float*)d_in[0];
    const float* W       = (const float*)d_in[1];
    const float* b       = (const float*)d_in[2];
    const int*   triples = (const int*)d_in[3];
    float*       out     = (float*)d_out;

    int n_nodes = in_sizes[0] / N_DIM;    // 100000
    int n_tr    = in_sizes[3] / 3;        // 200000
    int ntiles  = (n_nodes + 191) / 192;  // 521

    static int nsm = 0;
    if (nsm == 0) {
        cudaDeviceGetAttribute(&nsm, cudaDevAttrMultiProcessorCount, 0);
        cudaFuncSetAttribute(gemm_kernel, cudaFuncAttributeMaxDynamicSharedMemorySize, SMEM_BYTES);
    }
    int grid = (ntiles < nsm) ? ntiles : nsm;

    prep_kernel<<<256, 128>>>(W);
    gemm_kernel<<<grid, 384, SMEM_BYTES>>>(emb, n_nodes, ntiles, grid);
    gather_kernel<<<((n_tr + 1) / 2 + 255) / 256, 256>>>(triples, b, out, n_tr);
}

// round 15
// speedup vs baseline: 1.5941x; 1.4109x over previous
#include <cuda_runtime.h>
#include <cuda_fp16.h>
#include <cstdint>

#define N_DIM 512

// ---------------- scratch ----------------
__device__ __half g_Bh[128 * 512];             // fp16 W: rows 0..63 = Ws, 64..127 = Wo
__device__ __half g_P[(size_t)100000 * 128];   // fp16 P (25.6MB): [0..63]=s, [64..127]=o

// ---------------- smem geometry (2-stage, M=192 tile, K-chunk=64, fp16 128B rows) ----------------
#define A_STAGE_B 24576                        // 192 rows x 128B fp16
#define B_STAGE_B 16384                        // 128 rows x 128B fp16
#define B_OFF     (2 * A_STAGE_B)              // 49152
#define SMEM_BYTES (2 * A_STAGE_B + 2 * B_STAGE_B)   // 81920

// smem swizzle: byte col c in 128B row r -> c ^ ((r&7)*16)
#define FSW(r) ((uint32_t)(((r) & 7) << 4))

// ---------------- helpers ----------------
__device__ __forceinline__ void cp16(uint32_t saddr, const void* g) {
    asm volatile("cp.async.cg.shared.global [%0], [%1], 16;" :: "r"(saddr), "l"(g));
}
__device__ __forceinline__ void cp_commit() {
    asm volatile("cp.async.commit_group;" ::: "memory");
}
template <int N>
__device__ __forceinline__ void cp_wait() {
    asm volatile("cp.async.wait_group %0;" :: "n"(N) : "memory");
}
__device__ __forceinline__ uint32_t smem_u32(const void* p) {
    uint32_t a;
    asm("{ .reg .u64 t; cvta.to.shared.u64 t, %1; cvt.u32.u64 %0, t; }" : "=r"(a) : "l"(p));
    return a;
}
__device__ __forceinline__ void ldsm4(uint32_t r[4], uint32_t a) {
    asm volatile("ldmatrix.sync.aligned.m8n8.x4.shared.b16 {%0,%1,%2,%3}, [%4];"
                 : "=r"(r[0]), "=r"(r[1]), "=r"(r[2]), "=r"(r[3]) : "r"(a));
}
__device__ __forceinline__ void hmma16816(float d[4], const uint32_t a[4], uint32_t b0, uint32_t b1) {
    asm volatile("mma.sync.aligned.m16n8k16.row.col.f32.f16.f16.f32 "
                 "{%0,%1,%2,%3},{%4,%5,%6,%7},{%8,%9},{%0,%1,%2,%3};"
                 : "+f"(d[0]), "+f"(d[1]), "+f"(d[2]), "+f"(d[3])
                 : "r"(a[0]), "r"(a[1]), "r"(a[2]), "r"(a[3]), "r"(b0), "r"(b1));
}
__device__ __forceinline__ uint32_t pack_h2(float x, float y) {
    __half2 h = __floats2half2_rn(x, y);
    return *reinterpret_cast<uint32_t*>(&h);
}

// ---------------- kernel 0: W fp32 -> fp16, reorder to [128][512] ----------------
__global__ __launch_bounds__(128) void prep_kernel(const float* __restrict__ W) {
    int i = (blockIdx.x * 128 + threadIdx.x) * 2;
    if (i >= 128 * 512) return;
    int n = i >> 9, k = i & 511;
    const float* src = (n < 64) ? (W + n * 1024 + k) : (W + (n - 64) * 1024 + 512 + k);
    float2 v = *(const float2*)src;
    *(__half2*)&g_Bh[i] = __floats2half2_rn(v.x, v.y);
}

// ---------------- kernel 1: persistent P = emb @ B^T; fp16 A via coalesced LDG->cvt->STS.64 ----------------
__global__ __launch_bounds__(384, 1) void gemm_kernel(const float* __restrict__ emb,
                                                      int n_nodes, int ntiles, int grid) {
    extern __shared__ char smem[];
    const uint32_t sb = smem_u32(smem);
    const int tid = threadIdx.x;
    const int lane = tid & 31;
    const int wid = tid >> 5;
    const int wm = wid % 6;     // 6 M-tiles of 32 (CTA M=192)
    const int wn = wid / 6;     // 2 N-tiles of 64
    const int bid = blockIdx.x;

    const int ntiles_mine = (ntiles - bid + grid - 1) / grid;
    const int gtot = ntiles_mine * 8;

    // A granules: chunk = 192 rows x 16 granules(16B fp32) = 3072; thread t owns {t + 384 i}
    int arowv[8], acolv[8];
    #pragma unroll
    for (int i = 0; i < 8; i++) {
        int gidx = tid + i * 384;
        arowv[i] = gidx >> 4;
        acolv[i] = gidx & 15;
    }
    // B producer: threads 0..255, 4 granules each (R14 mapping, coalesced)
    const int brow = tid >> 1;
    const int bh   = tid & 1;

    float4 buf[8];              // A chunk in flight

    auto LDGA = [&](int g) {
        if (g >= gtot) return;
        const int tile = bid + (g >> 3) * grid;
        const int c = g & 7;
        const int ctaM = tile * 192;
        #pragma unroll
        for (int i = 0; i < 8; i++) {
            int ar = ctaM + arowv[i];
            if (ar >= n_nodes) ar = n_nodes - 1;
            buf[i] = *(const float4*)(emb + (size_t)ar * N_DIM + c * 64 + acolv[i] * 4);
        }
    };
    auto STSA = [&](int g) {
        if (g >= gtot) return;
        const uint32_t aOff = (g & 1) * A_STAGE_B;
        #pragma unroll
        for (int i = 0; i < 8; i++) {
            uint2 h = make_uint2(pack_h2(buf[i].x, buf[i].y), pack_h2(buf[i].z, buf[i].w));
            *(uint2*)(smem + aOff + arowv[i] * 128 +
                      (((uint32_t)(acolv[i] * 8)) ^ FSW(arowv[i]))) = h;
        }
    };
    auto ISSUEB = [&](int g) {
        if (g >= gtot || tid >= 256) return;
        const int c = g & 7;
        const uint32_t base = sb + B_OFF + (g & 1) * B_STAGE_B + brow * 128;
        const __half* src = g_Bh + brow * N_DIM + c * 64 + bh * 32;
        #pragma unroll
        for (int j = 0; j < 4; j++)
            cp16(base + (((uint32_t)(bh * 64 + j * 16)) ^ FSW(brow)), src + j * 8);
    };

    float acc[2][8][4];
    #pragma unroll
    for (int i = 0; i < 2; i++)
        #pragma unroll
        for (int j = 0; j < 8; j++)
            #pragma unroll
            for (int k = 0; k < 4; k++) acc[i][j][k] = 0.0f;

    // prologue
    LDGA(0);
    STSA(0);
    LDGA(1);
    ISSUEB(0); cp_commit();

    // consumer lane constants
    const int a_lrow = lane & 15;
    const uint32_t a_lcol = (uint32_t)((lane >> 4) * 16);
    const int b_lrow = (lane & 7) + ((lane >> 4) & 1) * 8;   // R3-proven B lane map
    const uint32_t b_lcol = (uint32_t)(((lane >> 3) & 1) * 16);

    for (int g = 0; g < gtot; g++) {
        cp_wait<0>();        // B of chunk g complete (pending == {g})
        __syncthreads();     // everyone's STS-A of g visible; slot (g+1)&1 free
        ISSUEB(g + 1); cp_commit();
        STSA(g + 1);         // from buf (LDG'd last iteration; latency covered by consume(g-1))
        LDGA(g + 2);         // refill buf

        const uint32_t aOff = (g & 1) * A_STAGE_B;
        const uint32_t bOff = B_OFF + (g & 1) * B_STAGE_B;

        #pragma unroll
        for (int ks = 0; ks < 4; ks++) {
            uint32_t afr[2][4];
            #pragma unroll
            for (int mt = 0; mt < 2; mt++) {
                const int row = wm * 32 + mt * 16 + a_lrow;
                ldsm4(afr[mt], sb + aOff + row * 128 + (((uint32_t)(ks * 32) + a_lcol) ^ FSW(row)));
            }
            uint32_t bfr[4][4];
            #pragma unroll
            for (int p = 0; p < 4; p++) {
                const int rn = wn * 64 + p * 16 + b_lrow;
                ldsm4(bfr[p], sb + bOff + rn * 128 + (((uint32_t)(ks * 32) + b_lcol) ^ FSW(rn)));
            }
            #pragma unroll
            for (int mt = 0; mt < 2; mt++)
                #pragma unroll
                for (int p = 0; p < 4; p++) {
                    hmma16816(acc[mt][2 * p],     afr[mt], bfr[p][0], bfr[p][1]);
                    hmma16816(acc[mt][2 * p + 1], afr[mt], bfr[p][2], bfr[p][3]);
                }
        }

        if ((g & 7) == 7) {
            const int ctaM = (bid + (g >> 3) * grid) * 192;
            #pragma unroll
            for (int mt = 0; mt < 2; mt++) {
                const int r0 = ctaM + wm * 32 + mt * 16 + (lane >> 2);
                const int r1 = r0 + 8;
                #pragma unroll
                for (int nf = 0; nf < 8; nf++) {
                    const int col = wn * 64 + nf * 8 + (lane & 3) * 2;
                    if (r0 < n_nodes)
                        *(uint32_t*)&g_P[(size_t)r0 * 128 + col] = pack_h2(acc[mt][nf][0], acc[mt][nf][1]);
                    if (r1 < n_nodes)
                        *(uint32_t*)&g_P[(size_t)r1 * 128 + col] = pack_h2(acc[mt][nf][2], acc[mt][nf][3]);
                    acc[mt][nf][0] = acc[mt][nf][1] = acc[mt][nf][2] = acc[mt][nf][3] = 0.0f;
                }
            }
        }
    }
}

// ---------------- kernel 2: per-triple gather-combine, 2 triples/thread, fp16 P ----------------
__global__ __launch_bounds__(256) void gather_kernel(const int* __restrict__ triples,
                                                     const float* __restrict__ b,
                                                     float* __restrict__ out, int n) {
    int t = blockIdx.x * blockDim.x + threadIdx.x;
    int half = (n + 1) >> 1;
    if (t >= half) return;
    int t2 = t + half;
    bool has2 = t2 < n;

    int s1 = triples[t],  r1 = triples[n + t],  o1 = triples[2 * n + t];
    int s2 = 0, r2 = 0, o2 = 0;
    if (has2) { s2 = triples[t2]; r2 = triples[n + t2]; o2 = triples[2 * n + t2]; }

    __half a1 = __ldg(&g_P[(size_t)s1 * 128 + r1]);
    __half c1 = __ldg(&g_P[(size_t)o1 * 128 + 64 + r1]);
    __half a2 = __float2half(0.f), c2 = __float2half(0.f);
    if (has2) {
        a2 = __ldg(&g_P[(size_t)s2 * 128 + r2]);
        c2 = __ldg(&g_P[(size_t)o2 * 128 + 64 + r2]);
    }

    out[t] = __half2float(a1) + __half2float(c1) + __ldg(&b[r1]);
    if (has2) out[t2] = __half2float(a2) + __half2float(c2) + __ldg(&b[r2]);
}

extern "C" void kernel_launch(void* const* d_in, const int* in_sizes, int n_in,
                              void* d_out, int out_size)
{
    const float* emb     = (const float*)d_in[0];
    const float* W       = (const float*)d_in[1];
    const float* b       = (const float*)d_in[2];
    const int*   triples = (const int*)d_in[3];
    float*       out     = (float*)d_out;

    int n_nodes = in_sizes[0] / N_DIM;    // 100000
    int n_tr    = in_sizes[3] / 3;        // 200000
    int ntiles  = (n_nodes + 191) / 192;  // 521

    static int nsm = 0;
    if (nsm == 0) {
        cudaDeviceGetAttribute(&nsm, cudaDevAttrMultiProcessorCount, 0);
        cudaFuncSetAttribute(gemm_kernel, cudaFuncAttributeMaxDynamicSharedMemorySize, SMEM_BYTES);
    }
    int grid = (ntiles < nsm) ? ntiles : nsm;

    prep_kernel<<<256, 128>>>(W);
    gemm_kernel<<<grid, 384, SMEM_BYTES>>>(emb, n_nodes, ntiles, grid);
    gather_kernel<<<((n_tr + 1) / 2 + 255) / 256, 256>>>(triples, b, out, n_tr);
}

// round 16
// speedup vs baseline: 1.7482x; 1.0967x over previous
#include <cuda_runtime.h>
#include <cuda_fp16.h>
#include <cstdint>

#define N_DIM 512

// ---------------- scratch ----------------
__device__ uint4  g_Bimg4[8192];               // 128KB pre-swizzled fp16 B image (smem-ready)
__device__ __half g_P[(size_t)100000 * 128];   // fp16 P (25.6MB): [0..63]=s, [64..127]=o

// ---------------- smem layout ----------------
// [0, 131072)       B static: 128 rows x 1024B fp16, granule-swizzled
// [131072, +49152)  A: 2 stages x 192 rows x 128B fp16
#define A_OFF      131072
#define A_STAGE_B  24576
#define SMEM_BYTES (131072 + 2 * A_STAGE_B)    // 180224

// swizzle: byte col c in row r -> c ^ ((r&7)*16)   (granule-level XOR of bits 4..6)
#define FSW(r) ((uint32_t)(((r) & 7) << 4))

// ---------------- helpers ----------------
__device__ __forceinline__ void cp16(uint32_t saddr, const void* g) {
    asm volatile("cp.async.cg.shared.global [%0], [%1], 16;" :: "r"(saddr), "l"(g));
}
__device__ __forceinline__ void cp_commit() {
    asm volatile("cp.async.commit_group;" ::: "memory");
}
template <int N>
__device__ __forceinline__ void cp_wait() {
    asm volatile("cp.async.wait_group %0;" :: "n"(N) : "memory");
}
__device__ __forceinline__ uint32_t smem_u32(const void* p) {
    uint32_t a;
    asm("{ .reg .u64 t; cvta.to.shared.u64 t, %1; cvt.u32.u64 %0, t; }" : "=r"(a) : "l"(p));
    return a;
}
__device__ __forceinline__ void ldsm4(uint32_t r[4], uint32_t a) {
    asm volatile("ldmatrix.sync.aligned.m8n8.x4.shared.b16 {%0,%1,%2,%3}, [%4];"
                 : "=r"(r[0]), "=r"(r[1]), "=r"(r[2]), "=r"(r[3]) : "r"(a));
}
__device__ __forceinline__ void hmma16816(float d[4], const uint32_t a[4], uint32_t b0, uint32_t b1) {
    asm volatile("mma.sync.aligned.m16n8k16.row.col.f32.f16.f16.f32 "
                 "{%0,%1,%2,%3},{%4,%5,%6,%7},{%8,%9},{%0,%1,%2,%3};"
                 : "+f"(d[0]), "+f"(d[1]), "+f"(d[2]), "+f"(d[3])
                 : "r"(a[0]), "r"(a[1]), "r"(a[2]), "r"(a[3]), "r"(b0), "r"(b1));
}
__device__ __forceinline__ uint32_t pack_h2(float x, float y) {
    __half2 h = __floats2half2_rn(x, y);
    return *reinterpret_cast<uint32_t*>(&h);
}

// ---------------- kernel 0: W fp32 -> pre-swizzled fp16 B image ----------------
// B row n (n<64: Ws[n], else Wo[n-64]), granule gk (8 fp16) stored at index n*64 + (gk ^ (n&7)).
__global__ __launch_bounds__(128) void prep_kernel(const float* __restrict__ W) {
    int i = blockIdx.x * 128 + threadIdx.x;    // granule id, 8192 total
    if (i >= 8192) return;
    int n = i >> 6, gk = i & 63;
    const float* src = (n < 64) ? (W + (size_t)n * 1024 + gk * 8)
                                : (W + (size_t)(n - 64) * 1024 + 512 + gk * 8);
    float4 v0 = *(const float4*)src;
    float4 v1 = *(const float4*)(src + 4);
    uint4 h;
    h.x = pack_h2(v0.x, v0.y); h.y = pack_h2(v0.z, v0.w);
    h.z = pack_h2(v1.x, v1.y); h.w = pack_h2(v1.z, v1.w);
    g_Bimg4[n * 64 + (gk ^ (n & 7))] = h;
}

// ---------------- kernel 1: persistent P = emb @ B^T; B resident in smem, A 2-stage reg hop ----------------
__global__ __launch_bounds__(384, 1) void gemm_kernel(const float* __restrict__ emb,
                                                      int n_nodes, int ntiles, int grid) {
    extern __shared__ char smem[];
    const uint32_t sb = smem_u32(smem);
    const int tid = threadIdx.x;
    const int lane = tid & 31;
    const int wid = tid >> 5;
    const int wm = wid % 6;     // 6 M-tiles of 32 (CTA M=192)
    const int wn = wid / 6;     // 2 N-tiles of 64
    const int bid = blockIdx.x;

    const int ntiles_mine = (ntiles - bid + grid - 1) / grid;
    const int gtot = ntiles_mine * 8;

    // ---- prologue: copy static B image (128KB) into smem via cp.async ----
    for (int i = tid; i < 8192; i += 384)
        cp16(sb + i * 16, &g_Bimg4[i]);
    cp_commit();

    // A granules: chunk = 192 rows x 16 fp32-granules = 3072; thread t owns {t + 384 i}
    int arowv[8], acolv[8];
    #pragma unroll
    for (int i = 0; i < 8; i++) {
        int gidx = tid + i * 384;
        arowv[i] = gidx >> 4;
        acolv[i] = gidx & 15;
    }

    float4 buf[8];              // A chunk in flight

    auto LDGA = [&](int g) {
        if (g >= gtot) return;
        const int tile = bid + (g >> 3) * grid;
        const int c = g & 7;
        const int ctaM = tile * 192;
        #pragma unroll
        for (int i = 0; i < 8; i++) {
            int ar = ctaM + arowv[i];
            if (ar >= n_nodes) ar = n_nodes - 1;
            buf[i] = *(const float4*)(emb + (size_t)ar * N_DIM + c * 64 + acolv[i] * 4);
        }
    };
    auto STSA = [&](int g) {
        if (g >= gtot) return;
        const uint32_t aOff = A_OFF + (g & 1) * A_STAGE_B;
        #pragma unroll
        for (int i = 0; i < 8; i++) {
            uint2 h = make_uint2(pack_h2(buf[i].x, buf[i].y), pack_h2(buf[i].z, buf[i].w));
            *(uint2*)(smem + aOff + arowv[i] * 128 +
                      (((uint32_t)(acolv[i] * 8)) ^ FSW(arowv[i]))) = h;
        }
    };

    float acc[2][8][4];
    #pragma unroll
    for (int i = 0; i < 2; i++)
        #pragma unroll
        for (int j = 0; j < 8; j++)
            #pragma unroll
            for (int k = 0; k < 4; k++) acc[i][j][k] = 0.0f;

    // prologue A: stage chunk 0, hold chunk 1 in regs
    LDGA(0);
    STSA(0);
    LDGA(1);
    cp_wait<0>();        // B image resident
    __syncthreads();     // B copy + everyone's STSA(0) visible

    // consumer lane constants
    const int a_lrow = lane & 15;
    const uint32_t a_lcol = (uint32_t)((lane >> 4) * 16);
    const int b_lrow = (lane & 7) + ((lane >> 4) & 1) * 8;   // R3-proven B lane map
    const uint32_t b_lcol = (uint32_t)(((lane >> 3) & 1) * 16);

    for (int g = 0; g < gtot; g++) {
        // entry invariant: slot g&1 holds chunk g (visible); buf holds chunk g+1
        STSA(g + 1);     // writes slot (g+1)&1 (chunk g-1's, consumed before last barrier)
        LDGA(g + 2);     // refill buf (WAR after STSA in program order)

        const uint32_t aOff = A_OFF + (g & 1) * A_STAGE_B;
        const int c = g & 7;

        #pragma unroll
        for (int ks = 0; ks < 4; ks++) {
            uint32_t afr[2][4];
            #pragma unroll
            for (int mt = 0; mt < 2; mt++) {
                const int row = wm * 32 + mt * 16 + a_lrow;
                ldsm4(afr[mt], sb + aOff + row * 128 + (((uint32_t)(ks * 32) + a_lcol) ^ FSW(row)));
            }
            uint32_t bfr[4][4];
            #pragma unroll
            for (int p = 0; p < 4; p++) {
                const int rn = wn * 64 + p * 16 + b_lrow;
                ldsm4(bfr[p], sb + rn * 1024 +
                              (((uint32_t)(c * 128 + ks * 32) + b_lcol) ^ FSW(rn)));
            }
            #pragma unroll
            for (int mt = 0; mt < 2; mt++)
                #pragma unroll
                for (int p = 0; p < 4; p++) {
                    hmma16816(acc[mt][2 * p],     afr[mt], bfr[p][0], bfr[p][1]);
                    hmma16816(acc[mt][2 * p + 1], afr[mt], bfr[p][2], bfr[p][3]);
                }
        }

        if ((g & 7) == 7) {
            const int ctaM = (bid + (g >> 3) * grid) * 192;
            #pragma unroll
            for (int mt = 0; mt < 2; mt++) {
                const int r0 = ctaM + wm * 32 + mt * 16 + (lane >> 2);
                const int r1 = r0 + 8;
                #pragma unroll
                for (int nf = 0; nf < 8; nf++) {
                    const int col = wn * 64 + nf * 8 + (lane & 3) * 2;
                    if (r0 < n_nodes)
                        *(uint32_t*)&g_P[(size_t)r0 * 128 + col] = pack_h2(acc[mt][nf][0], acc[mt][nf][1]);
                    if (r1 < n_nodes)
                        *(uint32_t*)&g_P[(size_t)r1 * 128 + col] = pack_h2(acc[mt][nf][2], acc[mt][nf][3]);
                    acc[mt][nf][0] = acc[mt][nf][1] = acc[mt][nf][2] = acc[mt][nf][3] = 0.0f;
                }
            }
        }

        __syncthreads();  // consume(g) done by all warps; STSA(g+1) visible -> next iter invariant
    }
}

// ---------------- kernel 2: per-triple gather-combine, 2 triples/thread, fp16 P ----------------
__global__ __launch_bounds__(256) void gather_kernel(const int* __restrict__ triples,
                                                     const float* __restrict__ b,
                                                     float* __restrict__ out, int n) {
    int t = blockIdx.x * blockDim.x + threadIdx.x;
    int half = (n + 1) >> 1;
    if (t >= half) return;
    int t2 = t + half;
    bool has2 = t2 < n;

    int s1 = triples[t],  r1 = triples[n + t],  o1 = triples[2 * n + t];
    int s2 = 0, r2 = 0, o2 = 0;
    if (has2) { s2 = triples[t2]; r2 = triples[n + t2]; o2 = triples[2 * n + t2]; }

    __half a1 = __ldg(&g_P[(size_t)s1 * 128 + r1]);
    __half c1 = __ldg(&g_P[(size_t)o1 * 128 + 64 + r1]);
    __half a2 = __float2half(0.f), c2 = __float2half(0.f);
    if (has2) {
        a2 = __ldg(&g_P[(size_t)s2 * 128 + r2]);
        c2 = __ldg(&g_P[(size_t)o2 * 128 + 64 + r2]);
    }

    out[t] = __half2float(a1) + __half2float(c1) + __ldg(&b[r1]);
    if (has2) out[t2] = __half2float(a2) + __half2float(c2) + __ldg(&b[r2]);
}

extern "C" void kernel_launch(void* const* d_in, const int* in_sizes, int n_in,
                              void* d_out, int out_size)
{
    const float* emb     = (const float*)d_in[0];
    const float* W       = (const float*)d_in[1];
    const float* b       = (const float*)d_in[2];
    const int*   triples = (const int*)d_in[3];
    float*       out     = (float*)d_out;

    int n_nodes = in_sizes[0] / N_DIM;    // 100000
    int n_tr    = in_sizes[3] / 3;        // 200000
    int ntiles  = (n_nodes + 191) / 192;  // 521

    static int nsm = 0;
    if (nsm == 0) {
        cudaDeviceGetAttribute(&nsm, cudaDevAttrMultiProcessorCount, 0);
        cudaFuncSetAttribute(gemm_kernel, cudaFuncAttributeMaxDynamicSharedMemorySize, SMEM_BYTES);
    }
    int grid = (ntiles < nsm) ? ntiles : nsm;

    prep_kernel<<<64, 128>>>(W);
    gemm_kernel<<<grid, 384, SMEM_BYTES>>>(emb, n_nodes, ntiles, grid);
    gather_kernel<<<((n_tr + 1) / 2 + 255) / 256, 256>>>(triples, b, out, n_tr);
}